// round 8
// baseline (speedup 1.0000x reference)
#include <cuda_runtime.h>
#include <cuda_fp16.h>
#include <cstdint>

#define NMAX   100096
#define EMAX   1600000
#define INF_   128
#define OC_    128
#define HEADS_ 4
#define OUTF_  32
#define NEG_SLOPE_ 0.2f

// ---------------- scratch ----------------
__device__ __half g_WhH[(size_t)NMAX * OC_];    // 25.6 MB (L2-resident)
__device__ float g_ssrc[(size_t)NMAX * HEADS_];
__device__ float g_sdst[(size_t)NMAX * HEADS_];
__device__ float g_attn[(size_t)NMAX * HEADS_]; // unnormalized exp(nscore)
__device__ float g_gsum[HEADS_];
__device__ int   g_deg[NMAX];
__device__ int   g_incl[NMAX];
__device__ int   g_rowptr[NMAX];
__device__ int   g_cursor[NMAX];
__device__ int   g_esrc[EMAX];
__device__ int   g_bsum[128];
__device__ int   g_boff[128];

__device__ __forceinline__ float neg_inf() { return __int_as_float(0xFF800000); }

__device__ __forceinline__ float to_tf32(float x) {
    float r;
    asm("cvt.rna.tf32.f32 %0, %1;" : "=f"(r) : "f"(x));
    return r;
}

__device__ __forceinline__ void mma_tf32(float* c, const uint32_t* a, const uint32_t* b) {
    asm volatile(
        "mma.sync.aligned.m16n8k8.row.col.f32.tf32.tf32.f32 "
        "{%0,%1,%2,%3},{%4,%5,%6,%7},{%8,%9},{%0,%1,%2,%3};"
        : "+f"(c[0]), "+f"(c[1]), "+f"(c[2]), "+f"(c[3])
        : "r"(a[0]), "r"(a[1]), "r"(a[2]), "r"(a[3]), "r"(b[0]), "r"(b[1]));
}

// ---------------- init: zero deg, reset global sums ------------------------
__global__ void init_kernel(int N) {
    int i = blockIdx.x * blockDim.x + threadIdx.x;
    if (i < N) g_deg[i] = 0;
    if (i == 0) {
        #pragma unroll
        for (int h = 0; h < HEADS_; h++) g_gsum[h] = 0.f;
    }
}

// ---------------- degree histogram (4 edges per thread) --------------------
__global__ void count_kernel(const int* __restrict__ ei, int E) {
    int t = blockIdx.x * blockDim.x + threadIdx.x;
    int base = t * 4;
    if (base + 3 < E) {
        int4 d = *(const int4*)(ei + E + base);
        atomicAdd(&g_deg[d.x], 1); atomicAdd(&g_deg[d.y], 1);
        atomicAdd(&g_deg[d.z], 1); atomicAdd(&g_deg[d.w], 1);
    } else {
        for (int e = base; e < E; e++) atomicAdd(&g_deg[ei[E + e]], 1);
    }
}

// ---------------- 3-phase exclusive scan of degrees ------------------------
__global__ void scan1_kernel(int N) {
    __shared__ int s[1024];
    int tid = threadIdx.x;
    int i = blockIdx.x * 1024 + tid;
    s[tid] = (i < N) ? g_deg[i] : 0;
    __syncthreads();
    for (int o = 1; o < 1024; o <<= 1) {
        int t = (tid >= o) ? s[tid - o] : 0;
        __syncthreads();
        s[tid] += t;
        __syncthreads();
    }
    if (i < N) g_incl[i] = s[tid];
    if (tid == 1023) g_bsum[blockIdx.x] = s[1023];
}

// parallel scan of up to 128 block sums
__global__ void scan2_kernel(int nb) {
    __shared__ int wsum[4], woff[4];
    int tid = threadIdx.x;
    int lane = tid & 31, w = tid >> 5;
    int v = (tid < nb) ? g_bsum[tid] : 0;
    int x = v;
    #pragma unroll
    for (int o = 1; o < 32; o <<= 1) {
        int y = __shfl_up_sync(0xFFFFFFFFu, x, o);
        if (lane >= o) x += y;
    }
    if (lane == 31) wsum[w] = x;
    __syncthreads();
    if (tid == 0) {
        int acc = 0;
        #pragma unroll
        for (int i = 0; i < 4; i++) { woff[i] = acc; acc += wsum[i]; }
    }
    __syncthreads();
    if (tid < nb) g_boff[tid] = x - v + woff[w];
}

__global__ void scan3_kernel(int N) {
    int i = blockIdx.x * blockDim.x + threadIdx.x;
    if (i >= N) return;
    int start = g_incl[i] - g_deg[i] + g_boff[i >> 10];
    g_rowptr[i] = start;
    g_cursor[i] = start;
}

// ---------------- scatter src ids into CSR order ---------------------------
__global__ void scatter_kernel(const int* __restrict__ ei, int E) {
    int e = blockIdx.x * blockDim.x + threadIdx.x;
    if (e >= E) return;
    int src = ei[e];
    int dst = ei[E + e];
    int pos = atomicAdd(&g_cursor[dst], 1);
    g_esrc[pos] = src;
}

// ---------------- 3xTF32 MMA GEMM + fused scores; Wh stored fp16 -----------
__global__ __launch_bounds__(256) void gemm_kernel(
    const float* __restrict__ A, const float* __restrict__ B,
    const float* __restrict__ av_g, int N)
{
    __shared__ float AsH[16][136];
    __shared__ float AsL[16][136];
    __shared__ float BsH[16][136];
    __shared__ float BsL[16][136];
    __shared__ float sA[256];       // attention vector a: [head][src32|dst32]

    int tid = threadIdx.x;
    int lane = tid & 31, wid = tid >> 5;
    int g = lane >> 2, t = lane & 3;
    int wm = (wid & 3) * 32;
    int wn = (wid >> 2) * 64;
    int br = blockIdx.x * 128;

    sA[tid] = av_g[tid];

    int arow = tid >> 1;
    int akofs = (tid & 1) * 8;
    int bk = tid >> 4;
    int bn = (tid & 15) * 8;

    float c[2][8][4];
    #pragma unroll
    for (int mt = 0; mt < 2; mt++)
        #pragma unroll
        for (int nt = 0; nt < 8; nt++)
            #pragma unroll
            for (int q = 0; q < 4; q++) c[mt][nt][q] = 0.f;

    for (int k0 = 0; k0 < INF_; k0 += 16) {
        float av[8] = {};
        int grow = br + arow;
        if (grow < N) {
            float4 a0 = *(const float4*)(A + (size_t)grow * INF_ + k0 + akofs);
            float4 a1 = *(const float4*)(A + (size_t)grow * INF_ + k0 + akofs + 4);
            av[0] = a0.x; av[1] = a0.y; av[2] = a0.z; av[3] = a0.w;
            av[4] = a1.x; av[5] = a1.y; av[6] = a1.z; av[7] = a1.w;
        }
        #pragma unroll
        for (int q = 0; q < 8; q++) {
            float hi = to_tf32(av[q]);
            AsH[akofs + q][arow] = hi;
            AsL[akofs + q][arow] = to_tf32(av[q] - hi);
        }

        float4 b0 = *(const float4*)(B + (size_t)(k0 + bk) * OC_ + bn);
        float4 b1 = *(const float4*)(B + (size_t)(k0 + bk) * OC_ + bn + 4);
        float bv[8] = { b0.x, b0.y, b0.z, b0.w, b1.x, b1.y, b1.z, b1.w };
        #pragma unroll
        for (int q = 0; q < 8; q++) {
            float hi = to_tf32(bv[q]);
            BsH[bk][bn + q] = hi;
            BsL[bk][bn + q] = to_tf32(bv[q] - hi);
        }

        __syncthreads();
        #pragma unroll
        for (int kk = 0; kk < 16; kk += 8) {
            uint32_t afh[2][4], afl[2][4];
            #pragma unroll
            for (int mt = 0; mt < 2; mt++) {
                int m = wm + mt * 16;
                afh[mt][0] = __float_as_uint(AsH[kk + t][m + g]);
                afh[mt][1] = __float_as_uint(AsH[kk + t][m + g + 8]);
                afh[mt][2] = __float_as_uint(AsH[kk + 4 + t][m + g]);
                afh[mt][3] = __float_as_uint(AsH[kk + 4 + t][m + g + 8]);
                afl[mt][0] = __float_as_uint(AsL[kk + t][m + g]);
                afl[mt][1] = __float_as_uint(AsL[kk + t][m + g + 8]);
                afl[mt][2] = __float_as_uint(AsL[kk + 4 + t][m + g]);
                afl[mt][3] = __float_as_uint(AsL[kk + 4 + t][m + g + 8]);
            }
            #pragma unroll
            for (int nt = 0; nt < 8; nt++) {
                int n = wn + nt * 8 + g;
                uint32_t bfh[2], bfl[2];
                bfh[0] = __float_as_uint(BsH[kk + t][n]);
                bfh[1] = __float_as_uint(BsH[kk + 4 + t][n]);
                bfl[0] = __float_as_uint(BsL[kk + t][n]);
                bfl[1] = __float_as_uint(BsL[kk + 4 + t][n]);
                #pragma unroll
                for (int mt = 0; mt < 2; mt++) {
                    mma_tf32(c[mt][nt], afl[mt], bfh);   // lo*hi
                    mma_tf32(c[mt][nt], afh[mt], bfl);   // hi*lo
                    mma_tf32(c[mt][nt], afh[mt], bfh);   // hi*hi
                }
            }
        }
        __syncthreads();
    }

    // ---- store Wh as fp16 (only consumer is the aggregate gather) ----
    #pragma unroll
    for (int mt = 0; mt < 2; mt++) {
        #pragma unroll
        for (int nt = 0; nt < 8; nt++) {
            int row0 = br + wm + mt * 16 + g;
            int col = wn + nt * 8 + 2 * t;
            if (row0 < N)
                *(__half2*)(g_WhH + (size_t)row0 * OC_ + col) =
                    __floats2half2_rn(c[mt][nt][0], c[mt][nt][1]);
            int row1 = row0 + 8;
            if (row1 < N)
                *(__half2*)(g_WhH + (size_t)row1 * OC_ + col) =
                    __floats2half2_rn(c[mt][nt][2], c[mt][nt][3]);
        }
    }

    // ---- fused scores from register fragments (fp32) ----
    float ds[2][2][2] = {}, dd[2][2][2] = {};
    #pragma unroll
    for (int nt = 0; nt < 8; nt++) {
        int col0 = wn + nt * 8 + 2 * t;
        int hgl = col0 >> 5;
        int j = col0 & 31;
        float as0 = sA[hgl * 64 + j],      as1 = sA[hgl * 64 + j + 1];
        float ad0 = sA[hgl * 64 + 32 + j], ad1 = sA[hgl * 64 + 33 + j];
        int hh = nt >> 2;
        #pragma unroll
        for (int mt = 0; mt < 2; mt++) {
            ds[mt][0][hh] += c[mt][nt][0] * as0 + c[mt][nt][1] * as1;
            ds[mt][1][hh] += c[mt][nt][2] * as0 + c[mt][nt][3] * as1;
            dd[mt][0][hh] += c[mt][nt][0] * ad0 + c[mt][nt][1] * ad1;
            dd[mt][1][hh] += c[mt][nt][2] * ad0 + c[mt][nt][3] * ad1;
        }
    }
    int hbase = wn >> 5;
    #pragma unroll
    for (int mt = 0; mt < 2; mt++)
        #pragma unroll
        for (int rh = 0; rh < 2; rh++)
            #pragma unroll
            for (int hh = 0; hh < 2; hh++) {
                float vs = ds[mt][rh][hh];
                float vd = dd[mt][rh][hh];
                vs += __shfl_xor_sync(0xFFFFFFFFu, vs, 1);
                vs += __shfl_xor_sync(0xFFFFFFFFu, vs, 2);
                vd += __shfl_xor_sync(0xFFFFFFFFu, vd, 1);
                vd += __shfl_xor_sync(0xFFFFFFFFu, vd, 2);
                if (t == 0) {
                    int row = br + wm + mt * 16 + g + rh * 8;
                    if (row < N) {
                        g_ssrc[row * HEADS_ + hbase + hh] = vs;
                        g_sdst[row * HEADS_ + hbase + hh] = vd;
                    }
                }
            }
}

// ---------------- pull segment-max + leaky + exp + global sum --------------
__global__ __launch_bounds__(256) void nodemax_kernel(int N) {
    __shared__ float ssum[8][4];
    int gw   = (blockIdx.x * blockDim.x + threadIdx.x) >> 5;
    int lane = threadIdx.x & 31;
    int wrp  = threadIdx.x >> 5;
    bool valid = gw < N;

    float ni = neg_inf();
    float e0 = 0.f, e1 = 0.f, e2 = 0.f, e3 = 0.f;
    if (valid) {
        int start = g_rowptr[gw];
        int cnt   = g_deg[gw];
        float m0 = ni, m1 = ni, m2 = ni, m3 = ni;
        for (int i = lane; i < cnt; i += 32) {
            int s = g_esrc[start + i];
            float4 v = *(const float4*)(g_ssrc + (size_t)s * HEADS_);
            m0 = fmaxf(m0, v.x); m1 = fmaxf(m1, v.y);
            m2 = fmaxf(m2, v.z); m3 = fmaxf(m3, v.w);
        }
        #pragma unroll
        for (int o = 16; o >= 1; o >>= 1) {
            m0 = fmaxf(m0, __shfl_xor_sync(0xFFFFFFFFu, m0, o));
            m1 = fmaxf(m1, __shfl_xor_sync(0xFFFFFFFFu, m1, o));
            m2 = fmaxf(m2, __shfl_xor_sync(0xFFFFFFFFu, m2, o));
            m3 = fmaxf(m3, __shfl_xor_sync(0xFFFFFFFFu, m3, o));
        }
        if (lane == 0) {
            float4 sd = *(const float4*)(g_sdst + (size_t)gw * HEADS_);
            float v0 = m0 + sd.x; v0 = v0 > 0.f ? v0 : NEG_SLOPE_ * v0;
            float v1 = m1 + sd.y; v1 = v1 > 0.f ? v1 : NEG_SLOPE_ * v1;
            float v2 = m2 + sd.z; v2 = v2 > 0.f ? v2 : NEG_SLOPE_ * v2;
            float v3 = m3 + sd.w; v3 = v3 > 0.f ? v3 : NEG_SLOPE_ * v3;
            e0 = __expf(v0); e1 = __expf(v1);
            e2 = __expf(v2); e3 = __expf(v3);
            *(float4*)(g_attn + (size_t)gw * HEADS_) = make_float4(e0, e1, e2, e3);
        }
    }
    if (lane == 0) {
        ssum[wrp][0] = e0; ssum[wrp][1] = e1;
        ssum[wrp][2] = e2; ssum[wrp][3] = e3;
    }
    __syncthreads();
    if (threadIdx.x < 4) {
        float s = ssum[0][threadIdx.x];
        #pragma unroll
        for (int w = 1; w < 8; w++) s += ssum[w][threadIdx.x];
        atomicAdd(&g_gsum[threadIdx.x], s);
    }
}

// ---------------- pull aggregation: one node per 16-lane group -------------
// 16 lanes x uint4 (8 halfs) = full 256B row per LDG.128; 2 nodes per warp.
__global__ __launch_bounds__(256) void aggregate_kernel(float* __restrict__ out, int N) {
    int gn = (blockIdx.x * blockDim.x + threadIdx.x) >> 4;  // node id
    int l  = threadIdx.x & 15;                               // lane in group
    if (gn >= N) return;
    int start = g_rowptr[gn];
    int end   = start + g_deg[gn];

    float a0 = 0.f, a1 = 0.f, a2 = 0.f, a3 = 0.f;
    float a4 = 0.f, a5 = 0.f, a6 = 0.f, a7 = 0.f;
    const __half* whl = g_WhH + l * 8;      // cols [l*8, l*8+8)
    int i = start;
    for (; i + 3 < end; i += 4) {
        uint4 u0 = *(const uint4*)(whl + (size_t)g_esrc[i + 0] * OC_);
        uint4 u1 = *(const uint4*)(whl + (size_t)g_esrc[i + 1] * OC_);
        uint4 u2 = *(const uint4*)(whl + (size_t)g_esrc[i + 2] * OC_);
        uint4 u3 = *(const uint4*)(whl + (size_t)g_esrc[i + 3] * OC_);
        float2 p;
        p = __half22float2(*(__half2*)&u0.x); a0 += p.x; a1 += p.y;
        p = __half22float2(*(__half2*)&u0.y); a2 += p.x; a3 += p.y;
        p = __half22float2(*(__half2*)&u0.z); a4 += p.x; a5 += p.y;
        p = __half22float2(*(__half2*)&u0.w); a6 += p.x; a7 += p.y;
        p = __half22float2(*(__half2*)&u1.x); a0 += p.x; a1 += p.y;
        p = __half22float2(*(__half2*)&u1.y); a2 += p.x; a3 += p.y;
        p = __half22float2(*(__half2*)&u1.z); a4 += p.x; a5 += p.y;
        p = __half22float2(*(__half2*)&u1.w); a6 += p.x; a7 += p.y;
        p = __half22float2(*(__half2*)&u2.x); a0 += p.x; a1 += p.y;
        p = __half22float2(*(__half2*)&u2.y); a2 += p.x; a3 += p.y;
        p = __half22float2(*(__half2*)&u2.z); a4 += p.x; a5 += p.y;
        p = __half22float2(*(__half2*)&u2.w); a6 += p.x; a7 += p.y;
        p = __half22float2(*(__half2*)&u3.x); a0 += p.x; a1 += p.y;
        p = __half22float2(*(__half2*)&u3.y); a2 += p.x; a3 += p.y;
        p = __half22float2(*(__half2*)&u3.z); a4 += p.x; a5 += p.y;
        p = __half22float2(*(__half2*)&u3.w); a6 += p.x; a7 += p.y;
    }
    for (; i < end; i++) {
        uint4 u = *(const uint4*)(whl + (size_t)g_esrc[i] * OC_);
        float2 p;
        p = __half22float2(*(__half2*)&u.x); a0 += p.x; a1 += p.y;
        p = __half22float2(*(__half2*)&u.y); a2 += p.x; a3 += p.y;
        p = __half22float2(*(__half2*)&u.z); a4 += p.x; a5 += p.y;
        p = __half22float2(*(__half2*)&u.w); a6 += p.x; a7 += p.y;
    }

    int head = l >> 2;                      // cols l*8.. within head (l*8)/32
    float attn = g_attn[(size_t)gn * HEADS_ + head] / g_gsum[head];
    float* op = out + (size_t)gn * OC_ + l * 8;
    *(float4*)(op)     = make_float4(a0 * attn, a1 * attn, a2 * attn, a3 * attn);
    *(float4*)(op + 4) = make_float4(a4 * attn, a5 * attn, a6 * attn, a7 * attn);
}

// ---------------- launch: R6 topology; gemm placed at launch index 5 -------
extern "C" void kernel_launch(void* const* d_in, const int* in_sizes, int n_in,
                              void* d_out, int out_size) {
    const float* h  = (const float*)d_in[0];
    const int*   ei = (const int*)d_in[1];
    const float* W  = (const float*)d_in[2];
    const float* a  = (const float*)d_in[3];
    float* out = (float*)d_out;

    int N = in_sizes[0] / INF_;
    int E = in_sizes[1] / 2;
    int nb = (N + 1023) / 1024;

    static cudaStream_t s2 = nullptr;
    static cudaEvent_t e0 = nullptr, e2 = nullptr;
    if (s2 == nullptr) {
        cudaStreamCreateWithFlags(&s2, cudaStreamNonBlocking);
        cudaEventCreateWithFlags(&e0, cudaEventDisableTiming);
        cudaEventCreateWithFlags(&e2, cudaEventDisableTiming);
    }

    // fork: CSR build chain on s2, GEMM (+fused scores) on the main stream
    cudaEventRecord(e0, 0);
    cudaStreamWaitEvent(s2, e0, 0);

    // launches 0-4 (CSR head)
    init_kernel<<<(N + 255) / 256, 256, 0, s2>>>(N);
    count_kernel<<<((E + 3) / 4 + 255) / 256, 256, 0, s2>>>(ei, E);
    scan1_kernel<<<nb, 1024, 0, s2>>>(N);
    scan2_kernel<<<1, 128, 0, s2>>>(nb);
    scan3_kernel<<<(N + 255) / 256, 256, 0, s2>>>(N);

    // launch 5: gemm (profiled by ncu -s 5 -c 1)
    gemm_kernel<<<(N + 127) / 128, 256>>>(h, W, a, N);

    // CSR tail on s2 (still ordered after scan3 within s2)
    scatter_kernel<<<(E + 255) / 256, 256, 0, s2>>>(ei, E);
    cudaEventRecord(e2, s2);

    // join: nodemax needs CSR + scores
    cudaStreamWaitEvent(0, e2, 0);

    nodemax_kernel<<<(N * 32 + 255) / 256, 256>>>(N);
    aggregate_kernel<<<(N * 16 + 255) / 256, 256>>>(out, N);
}

// round 9
// speedup vs baseline: 1.0025x; 1.0025x over previous
#include <cuda_runtime.h>
#include <cuda_fp16.h>
#include <cstdint>

#define NMAX   100096
#define EMAX   1600000
#define INF_   128
#define OC_    128
#define HEADS_ 4
#define OUTF_  32
#define NEG_SLOPE_ 0.2f

// ---------------- scratch ----------------
__device__ __half g_WhH[(size_t)NMAX * OC_];    // 25.6 MB (L2-resident)
__device__ float g_ssrc[(size_t)NMAX * HEADS_];
__device__ float g_sdst[(size_t)NMAX * HEADS_];
__device__ float g_attn[(size_t)NMAX * HEADS_]; // unnormalized exp(nscore)
__device__ float g_gsum[HEADS_];
__device__ int   g_deg[NMAX];
__device__ int   g_incl[NMAX];
__device__ int   g_rowptr[NMAX];
__device__ int   g_cursor[NMAX];
__device__ int   g_esrc[EMAX];
__device__ int   g_bsum[128];
__device__ int   g_boff[128];

__device__ __forceinline__ float neg_inf() { return __int_as_float(0xFF800000); }

__device__ __forceinline__ float to_tf32(float x) {
    float r;
    asm("cvt.rna.tf32.f32 %0, %1;" : "=f"(r) : "f"(x));
    return r;
}

__device__ __forceinline__ void mma_tf32(float* c, const uint32_t* a, const uint32_t* b) {
    asm volatile(
        "mma.sync.aligned.m16n8k8.row.col.f32.tf32.tf32.f32 "
        "{%0,%1,%2,%3},{%4,%5,%6,%7},{%8,%9},{%0,%1,%2,%3};"
        : "+f"(c[0]), "+f"(c[1]), "+f"(c[2]), "+f"(c[3])
        : "r"(a[0]), "r"(a[1]), "r"(a[2]), "r"(a[3]), "r"(b[0]), "r"(b[1]));
}

// ---------------- init: zero deg, reset global sums ------------------------
__global__ void init_kernel(int N) {
    int i = blockIdx.x * blockDim.x + threadIdx.x;
    if (i < N) g_deg[i] = 0;
    if (i == 0) {
        #pragma unroll
        for (int h = 0; h < HEADS_; h++) g_gsum[h] = 0.f;
    }
}

// ---------------- degree histogram (4 edges per thread) --------------------
__global__ void count_kernel(const int* __restrict__ ei, int E) {
    int t = blockIdx.x * blockDim.x + threadIdx.x;
    int base = t * 4;
    if (base + 3 < E) {
        int4 d = *(const int4*)(ei + E + base);
        atomicAdd(&g_deg[d.x], 1); atomicAdd(&g_deg[d.y], 1);
        atomicAdd(&g_deg[d.z], 1); atomicAdd(&g_deg[d.w], 1);
    } else {
        for (int e = base; e < E; e++) atomicAdd(&g_deg[ei[E + e]], 1);
    }
}

// ---------------- 3-phase exclusive scan of degrees ------------------------
__global__ void scan1_kernel(int N) {
    __shared__ int s[1024];
    int tid = threadIdx.x;
    int i = blockIdx.x * 1024 + tid;
    s[tid] = (i < N) ? g_deg[i] : 0;
    __syncthreads();
    for (int o = 1; o < 1024; o <<= 1) {
        int t = (tid >= o) ? s[tid - o] : 0;
        __syncthreads();
        s[tid] += t;
        __syncthreads();
    }
    if (i < N) g_incl[i] = s[tid];
    if (tid == 1023) g_bsum[blockIdx.x] = s[1023];
}

// parallel scan of up to 128 block sums
__global__ void scan2_kernel(int nb) {
    __shared__ int wsum[4], woff[4];
    int tid = threadIdx.x;
    int lane = tid & 31, w = tid >> 5;
    int v = (tid < nb) ? g_bsum[tid] : 0;
    int x = v;
    #pragma unroll
    for (int o = 1; o < 32; o <<= 1) {
        int y = __shfl_up_sync(0xFFFFFFFFu, x, o);
        if (lane >= o) x += y;
    }
    if (lane == 31) wsum[w] = x;
    __syncthreads();
    if (tid == 0) {
        int acc = 0;
        #pragma unroll
        for (int i = 0; i < 4; i++) { woff[i] = acc; acc += wsum[i]; }
    }
    __syncthreads();
    if (tid < nb) g_boff[tid] = x - v + woff[w];
}

__global__ void scan3_kernel(int N) {
    int i = blockIdx.x * blockDim.x + threadIdx.x;
    if (i >= N) return;
    int start = g_incl[i] - g_deg[i] + g_boff[i >> 10];
    g_rowptr[i] = start;
    g_cursor[i] = start;
}

// ---------------- scatter src ids into CSR order ---------------------------
__global__ void scatter_kernel(const int* __restrict__ ei, int E) {
    int e = blockIdx.x * blockDim.x + threadIdx.x;
    if (e >= E) return;
    int src = ei[e];
    int dst = ei[E + e];
    int pos = atomicAdd(&g_cursor[dst], 1);
    g_esrc[pos] = src;
}

// ---------------- 3xTF32 MMA GEMM + fused scores; Wh stored fp16 -----------
__global__ __launch_bounds__(256) void gemm_kernel(
    const float* __restrict__ A, const float* __restrict__ B,
    const float* __restrict__ av_g, int N)
{
    __shared__ float AsH[16][136];
    __shared__ float AsL[16][136];
    __shared__ float BsH[16][136];
    __shared__ float BsL[16][136];
    __shared__ float sA[256];       // attention vector a: [head][src32|dst32]

    int tid = threadIdx.x;
    int lane = tid & 31, wid = tid >> 5;
    int g = lane >> 2, t = lane & 3;
    int wm = (wid & 3) * 32;
    int wn = (wid >> 2) * 64;
    int br = blockIdx.x * 128;

    sA[tid] = av_g[tid];

    int arow = tid >> 1;
    int akofs = (tid & 1) * 8;
    int bk = tid >> 4;
    int bn = (tid & 15) * 8;

    float c[2][8][4];
    #pragma unroll
    for (int mt = 0; mt < 2; mt++)
        #pragma unroll
        for (int nt = 0; nt < 8; nt++)
            #pragma unroll
            for (int q = 0; q < 4; q++) c[mt][nt][q] = 0.f;

    for (int k0 = 0; k0 < INF_; k0 += 16) {
        float av[8] = {};
        int grow = br + arow;
        if (grow < N) {
            float4 a0 = *(const float4*)(A + (size_t)grow * INF_ + k0 + akofs);
            float4 a1 = *(const float4*)(A + (size_t)grow * INF_ + k0 + akofs + 4);
            av[0] = a0.x; av[1] = a0.y; av[2] = a0.z; av[3] = a0.w;
            av[4] = a1.x; av[5] = a1.y; av[6] = a1.z; av[7] = a1.w;
        }
        #pragma unroll
        for (int q = 0; q < 8; q++) {
            float hi = to_tf32(av[q]);
            AsH[akofs + q][arow] = hi;
            AsL[akofs + q][arow] = to_tf32(av[q] - hi);
        }

        float4 b0 = *(const float4*)(B + (size_t)(k0 + bk) * OC_ + bn);
        float4 b1 = *(const float4*)(B + (size_t)(k0 + bk) * OC_ + bn + 4);
        float bv[8] = { b0.x, b0.y, b0.z, b0.w, b1.x, b1.y, b1.z, b1.w };
        #pragma unroll
        for (int q = 0; q < 8; q++) {
            float hi = to_tf32(bv[q]);
            BsH[bk][bn + q] = hi;
            BsL[bk][bn + q] = to_tf32(bv[q] - hi);
        }

        __syncthreads();
        #pragma unroll
        for (int kk = 0; kk < 16; kk += 8) {
            uint32_t afh[2][4], afl[2][4];
            #pragma unroll
            for (int mt = 0; mt < 2; mt++) {
                int m = wm + mt * 16;
                afh[mt][0] = __float_as_uint(AsH[kk + t][m + g]);
                afh[mt][1] = __float_as_uint(AsH[kk + t][m + g + 8]);
                afh[mt][2] = __float_as_uint(AsH[kk + 4 + t][m + g]);
                afh[mt][3] = __float_as_uint(AsH[kk + 4 + t][m + g + 8]);
                afl[mt][0] = __float_as_uint(AsL[kk + t][m + g]);
                afl[mt][1] = __float_as_uint(AsL[kk + t][m + g + 8]);
                afl[mt][2] = __float_as_uint(AsL[kk + 4 + t][m + g]);
                afl[mt][3] = __float_as_uint(AsL[kk + 4 + t][m + g + 8]);
            }
            #pragma unroll
            for (int nt = 0; nt < 8; nt++) {
                int n = wn + nt * 8 + g;
                uint32_t bfh[2], bfl[2];
                bfh[0] = __float_as_uint(BsH[kk + t][n]);
                bfh[1] = __float_as_uint(BsH[kk + 4 + t][n]);
                bfl[0] = __float_as_uint(BsL[kk + t][n]);
                bfl[1] = __float_as_uint(BsL[kk + 4 + t][n]);
                #pragma unroll
                for (int mt = 0; mt < 2; mt++) {
                    mma_tf32(c[mt][nt], afl[mt], bfh);   // lo*hi
                    mma_tf32(c[mt][nt], afh[mt], bfl);   // hi*lo
                    mma_tf32(c[mt][nt], afh[mt], bfh);   // hi*hi
                }
            }
        }
        __syncthreads();
    }

    // ---- store Wh as fp16 (only consumer is the aggregate gather) ----
    #pragma unroll
    for (int mt = 0; mt < 2; mt++) {
        #pragma unroll
        for (int nt = 0; nt < 8; nt++) {
            int row0 = br + wm + mt * 16 + g;
            int col = wn + nt * 8 + 2 * t;
            if (row0 < N)
                *(__half2*)(g_WhH + (size_t)row0 * OC_ + col) =
                    __floats2half2_rn(c[mt][nt][0], c[mt][nt][1]);
            int row1 = row0 + 8;
            if (row1 < N)
                *(__half2*)(g_WhH + (size_t)row1 * OC_ + col) =
                    __floats2half2_rn(c[mt][nt][2], c[mt][nt][3]);
        }
    }

    // ---- fused scores from register fragments (fp32) ----
    float ds[2][2][2] = {}, dd[2][2][2] = {};
    #pragma unroll
    for (int nt = 0; nt < 8; nt++) {
        int col0 = wn + nt * 8 + 2 * t;
        int hgl = col0 >> 5;
        int j = col0 & 31;
        float as0 = sA[hgl * 64 + j],      as1 = sA[hgl * 64 + j + 1];
        float ad0 = sA[hgl * 64 + 32 + j], ad1 = sA[hgl * 64 + 33 + j];
        int hh = nt >> 2;
        #pragma unroll
        for (int mt = 0; mt < 2; mt++) {
            ds[mt][0][hh] += c[mt][nt][0] * as0 + c[mt][nt][1] * as1;
            ds[mt][1][hh] += c[mt][nt][2] * as0 + c[mt][nt][3] * as1;
            dd[mt][0][hh] += c[mt][nt][0] * ad0 + c[mt][nt][1] * ad1;
            dd[mt][1][hh] += c[mt][nt][2] * ad0 + c[mt][nt][3] * ad1;
        }
    }
    int hbase = wn >> 5;
    #pragma unroll
    for (int mt = 0; mt < 2; mt++)
        #pragma unroll
        for (int rh = 0; rh < 2; rh++)
            #pragma unroll
            for (int hh = 0; hh < 2; hh++) {
                float vs = ds[mt][rh][hh];
                float vd = dd[mt][rh][hh];
                vs += __shfl_xor_sync(0xFFFFFFFFu, vs, 1);
                vs += __shfl_xor_sync(0xFFFFFFFFu, vs, 2);
                vd += __shfl_xor_sync(0xFFFFFFFFu, vd, 1);
                vd += __shfl_xor_sync(0xFFFFFFFFu, vd, 2);
                if (t == 0) {
                    int row = br + wm + mt * 16 + g + rh * 8;
                    if (row < N) {
                        g_ssrc[row * HEADS_ + hbase + hh] = vs;
                        g_sdst[row * HEADS_ + hbase + hh] = vd;
                    }
                }
            }
}

// ---------------- pull segment-max + leaky + exp + global sum --------------
__global__ __launch_bounds__(256) void nodemax_kernel(int N) {
    __shared__ float ssum[8][4];
    int gw   = (blockIdx.x * blockDim.x + threadIdx.x) >> 5;
    int lane = threadIdx.x & 31;
    int wrp  = threadIdx.x >> 5;
    bool valid = gw < N;

    float ni = neg_inf();
    float e0 = 0.f, e1 = 0.f, e2 = 0.f, e3 = 0.f;
    if (valid) {
        int start = g_rowptr[gw];
        int cnt   = g_deg[gw];
        float m0 = ni, m1 = ni, m2 = ni, m3 = ni;
        for (int i = lane; i < cnt; i += 32) {
            int s = g_esrc[start + i];
            float4 v = *(const float4*)(g_ssrc + (size_t)s * HEADS_);
            m0 = fmaxf(m0, v.x); m1 = fmaxf(m1, v.y);
            m2 = fmaxf(m2, v.z); m3 = fmaxf(m3, v.w);
        }
        #pragma unroll
        for (int o = 16; o >= 1; o >>= 1) {
            m0 = fmaxf(m0, __shfl_xor_sync(0xFFFFFFFFu, m0, o));
            m1 = fmaxf(m1, __shfl_xor_sync(0xFFFFFFFFu, m1, o));
            m2 = fmaxf(m2, __shfl_xor_sync(0xFFFFFFFFu, m2, o));
            m3 = fmaxf(m3, __shfl_xor_sync(0xFFFFFFFFu, m3, o));
        }
        if (lane == 0) {
            float4 sd = *(const float4*)(g_sdst + (size_t)gw * HEADS_);
            float v0 = m0 + sd.x; v0 = v0 > 0.f ? v0 : NEG_SLOPE_ * v0;
            float v1 = m1 + sd.y; v1 = v1 > 0.f ? v1 : NEG_SLOPE_ * v1;
            float v2 = m2 + sd.z; v2 = v2 > 0.f ? v2 : NEG_SLOPE_ * v2;
            float v3 = m3 + sd.w; v3 = v3 > 0.f ? v3 : NEG_SLOPE_ * v3;
            e0 = __expf(v0); e1 = __expf(v1);
            e2 = __expf(v2); e3 = __expf(v3);
            *(float4*)(g_attn + (size_t)gw * HEADS_) = make_float4(e0, e1, e2, e3);
        }
    }
    if (lane == 0) {
        ssum[wrp][0] = e0; ssum[wrp][1] = e1;
        ssum[wrp][2] = e2; ssum[wrp][3] = e3;
    }
    __syncthreads();
    if (threadIdx.x < 4) {
        float s = ssum[0][threadIdx.x];
        #pragma unroll
        for (int w = 1; w < 8; w++) s += ssum[w][threadIdx.x];
        atomicAdd(&g_gsum[threadIdx.x], s);
    }
}

// ---------------- pull aggregation: warp per node, lane-pair edge split ----
// Lanes 0-15 take even edges, 16-31 odd edges; each lane loads uint4 (8 halfs)
// for its column slice -> LDG.128 only, no intra-warp degree divergence.
__global__ __launch_bounds__(256) void aggregate_kernel(float* __restrict__ out, int N) {
    int gw   = (blockIdx.x * blockDim.x + threadIdx.x) >> 5;
    int lane = threadIdx.x & 31;
    if (gw >= N) return;
    int start = g_rowptr[gw];
    int end   = start + g_deg[gw];

    int half = lane >> 4;       // 0: even edges, 1: odd edges
    int l    = lane & 15;       // column-slice lane
    const __half* whl = g_WhH + l * 8;   // cols [l*8, l*8+8)

    float a0 = 0.f, a1 = 0.f, a2 = 0.f, a3 = 0.f;
    float a4 = 0.f, a5 = 0.f, a6 = 0.f, a7 = 0.f;

    int i = start;
    for (; i + 7 < end; i += 8) {
        uint4 u0 = *(const uint4*)(whl + (size_t)g_esrc[i + 0 + half] * OC_);
        uint4 u1 = *(const uint4*)(whl + (size_t)g_esrc[i + 2 + half] * OC_);
        uint4 u2 = *(const uint4*)(whl + (size_t)g_esrc[i + 4 + half] * OC_);
        uint4 u3 = *(const uint4*)(whl + (size_t)g_esrc[i + 6 + half] * OC_);
        float2 p;
        p = __half22float2(*(__half2*)&u0.x); a0 += p.x; a1 += p.y;
        p = __half22float2(*(__half2*)&u0.y); a2 += p.x; a3 += p.y;
        p = __half22float2(*(__half2*)&u0.z); a4 += p.x; a5 += p.y;
        p = __half22float2(*(__half2*)&u0.w); a6 += p.x; a7 += p.y;
        p = __half22float2(*(__half2*)&u1.x); a0 += p.x; a1 += p.y;
        p = __half22float2(*(__half2*)&u1.y); a2 += p.x; a3 += p.y;
        p = __half22float2(*(__half2*)&u1.z); a4 += p.x; a5 += p.y;
        p = __half22float2(*(__half2*)&u1.w); a6 += p.x; a7 += p.y;
        p = __half22float2(*(__half2*)&u2.x); a0 += p.x; a1 += p.y;
        p = __half22float2(*(__half2*)&u2.y); a2 += p.x; a3 += p.y;
        p = __half22float2(*(__half2*)&u2.z); a4 += p.x; a5 += p.y;
        p = __half22float2(*(__half2*)&u2.w); a6 += p.x; a7 += p.y;
        p = __half22float2(*(__half2*)&u3.x); a0 += p.x; a1 += p.y;
        p = __half22float2(*(__half2*)&u3.y); a2 += p.x; a3 += p.y;
        p = __half22float2(*(__half2*)&u3.z); a4 += p.x; a5 += p.y;
        p = __half22float2(*(__half2*)&u3.w); a6 += p.x; a7 += p.y;
    }
    for (; i + 1 < end; i += 2) {
        uint4 u = *(const uint4*)(whl + (size_t)g_esrc[i + half] * OC_);
        float2 p;
        p = __half22float2(*(__half2*)&u.x); a0 += p.x; a1 += p.y;
        p = __half22float2(*(__half2*)&u.y); a2 += p.x; a3 += p.y;
        p = __half22float2(*(__half2*)&u.z); a4 += p.x; a5 += p.y;
        p = __half22float2(*(__half2*)&u.w); a6 += p.x; a7 += p.y;
    }
    if (i < end && half == 0) {   // last odd edge: even-half only
        uint4 u = *(const uint4*)(whl + (size_t)g_esrc[i] * OC_);
        float2 p;
        p = __half22float2(*(__half2*)&u.x); a0 += p.x; a1 += p.y;
        p = __half22float2(*(__half2*)&u.y); a2 += p.x; a3 += p.y;
        p = __half22float2(*(__half2*)&u.z); a4 += p.x; a5 += p.y;
        p = __half22float2(*(__half2*)&u.w); a6 += p.x; a7 += p.y;
    }

    // merge even/odd halves (lane L <-> L+16 hold the same columns)
    a0 += __shfl_xor_sync(0xFFFFFFFFu, a0, 16);
    a1 += __shfl_xor_sync(0xFFFFFFFFu, a1, 16);
    a2 += __shfl_xor_sync(0xFFFFFFFFu, a2, 16);
    a3 += __shfl_xor_sync(0xFFFFFFFFu, a3, 16);
    a4 += __shfl_xor_sync(0xFFFFFFFFu, a4, 16);
    a5 += __shfl_xor_sync(0xFFFFFFFFu, a5, 16);
    a6 += __shfl_xor_sync(0xFFFFFFFFu, a6, 16);
    a7 += __shfl_xor_sync(0xFFFFFFFFu, a7, 16);

    int head = l >> 2;
    float attn = g_attn[(size_t)gw * HEADS_ + head] / g_gsum[head];
    if (half == 0) {
        float* op = out + (size_t)gw * OC_ + l * 8;
        *(float4*)(op)     = make_float4(a0 * attn, a1 * attn, a2 * attn, a3 * attn);
        *(float4*)(op + 4) = make_float4(a4 * attn, a5 * attn, a6 * attn, a7 * attn);
    }
}

// ---------------- launch: R7 topology -------------------------------------
extern "C" void kernel_launch(void* const* d_in, const int* in_sizes, int n_in,
                              void* d_out, int out_size) {
    const float* h  = (const float*)d_in[0];
    const int*   ei = (const int*)d_in[1];
    const float* W  = (const float*)d_in[2];
    const float* a  = (const float*)d_in[3];
    float* out = (float*)d_out;

    int N = in_sizes[0] / INF_;
    int E = in_sizes[1] / 2;
    int nb = (N + 1023) / 1024;

    static cudaStream_t s2 = nullptr;
    static cudaEvent_t e0 = nullptr, e2 = nullptr;
    if (s2 == nullptr) {
        cudaStreamCreateWithFlags(&s2, cudaStreamNonBlocking);
        cudaEventCreateWithFlags(&e0, cudaEventDisableTiming);
        cudaEventCreateWithFlags(&e2, cudaEventDisableTiming);
    }

    // fork: CSR build chain on s2, GEMM (+fused scores) on the main stream
    cudaEventRecord(e0, 0);
    cudaStreamWaitEvent(s2, e0, 0);

    init_kernel<<<(N + 255) / 256, 256, 0, s2>>>(N);
    count_kernel<<<((E + 3) / 4 + 255) / 256, 256, 0, s2>>>(ei, E);
    scan1_kernel<<<nb, 1024, 0, s2>>>(N);
    scan2_kernel<<<1, 128, 0, s2>>>(nb);
    scan3_kernel<<<(N + 255) / 256, 256, 0, s2>>>(N);
    scatter_kernel<<<(E + 255) / 256, 256, 0, s2>>>(ei, E);
    cudaEventRecord(e2, s2);

    gemm_kernel<<<(N + 127) / 128, 256>>>(h, W, a, N);

    // join: nodemax needs CSR + scores
    cudaStreamWaitEvent(0, e2, 0);

    nodemax_kernel<<<(N * 32 + 255) / 256, 256>>>(N);
    aggregate_kernel<<<(N * 32 + 255) / 256, 256>>>(out, N);
}